// round 5
// baseline (speedup 1.0000x reference)
#include <cuda_runtime.h>
#include <cuda_bf16.h>

// WaveletTransform: x (16,3,512,512) f32 ->
//   per (b,c): [x, up(LL), up(LH), up(HL), up(HH)] -> out (16,15,512,512) f32
// Haar 2x2 analysis + 2x bilinear upsample (half-pixel centers, clamp edges).
// No shared memory, no barriers: each thread recomputes the 12 Haar sub-cells
// it needs from clamped float2 loads (L1/L2-resident), then streams 10 STG.128.

#define BX 16           // threads x (each covers 2 sub-cell cols)
#define BY 8            // threads y
#define TSX 32          // sub-cells per block, x
#define TSY 8           // sub-cells per block, y

__global__ __launch_bounds__(BX * BY)
void wavelet_kernel(const float* __restrict__ x, float* __restrict__ out) {
    const int plane = blockIdx.z;           // b*3 + c
    const int b = plane / 3;
    const int c = plane - 3 * b;
    const float* __restrict__ xp = x + (size_t)plane * 512 * 512;
    float* __restrict__ op = out + ((size_t)b * 15 + (size_t)c * 5) * 512 * 512;

    // This thread owns sub-cells (sy, sxp) and (sy, sxp+1).
    const int sxp = blockIdx.x * TSX + 2 * threadIdx.x;   // [0,256) even
    const int sy  = blockIdx.y * TSY + threadIdx.y;       // [0,256)
    const size_t row_t = (size_t)(2 * sy) * 512;
    const size_t row_b = (size_t)(2 * sy + 1) * 512;
    const size_t colo  = (size_t)(2 * sxp);               // 16B aligned

    // ---- Band 0: passthrough copy of x (issued first, no dependencies) ----
    {
        const float4 t0 = *((const float4*)(xp + row_t + colo));
        const float4 t1 = *((const float4*)(xp + row_b + colo));
        __stcs((float4*)(op + row_t + colo), t0);
        __stcs((float4*)(op + row_b + colo), t1);
    }

    // Clamped sub-cell column indices jj=0..3 <-> sxp-1 .. sxp+2
    int jc[4];
    #pragma unroll
    for (int jj = 0; jj < 4; jj++) jc[jj] = min(max(sxp - 1 + jj, 0), 255);
    // Clamped sub-cell row indices rr=0..2 <-> sy-1 .. sy+1
    int rc[3];
    rc[0] = max(sy - 1, 0);
    rc[1] = sy;
    rc[2] = min(sy + 1, 255);

    // Horizontal interps: h[row][band][pos], 4 output cols per band per row
    float h[3][4][4];
    #pragma unroll
    for (int rr = 0; rr < 3; rr++) {
        const float* __restrict__ r0 = xp + (size_t)(2 * rc[rr]) * 512;
        const float* __restrict__ r1 = r0 + 512;
        // Haar bands for the 4 sub-cells of this sub-row
        float B[4][4];  // [band][jj]
        #pragma unroll
        for (int jj = 0; jj < 4; jj++) {
            const float2 t0 = *((const float2*)(r0 + 2 * jc[jj]));
            const float2 t1 = *((const float2*)(r1 + 2 * jc[jj]));
            const float e = t0.x + t0.y;   // a+b
            const float f = t1.x + t1.y;   // c+d
            const float g = t0.x - t0.y;   // a-b
            const float q = t1.x - t1.y;   // c-d
            B[0][jj] = (e + f) * 0.5f;     // LL
            B[1][jj] = (e - f) * 0.5f;     // LH
            B[2][jj] = (g + q) * 0.5f;     // HL
            B[3][jj] = (g - q) * 0.5f;     // HH
        }
        // even out: 0.25*prev + 0.75*cur ; odd: 0.75*cur + 0.25*next
        #pragma unroll
        for (int band = 0; band < 4; band++) {
            h[rr][band][0] = 0.25f * B[band][0] + 0.75f * B[band][1];
            h[rr][band][1] = 0.75f * B[band][1] + 0.25f * B[band][2];
            h[rr][band][2] = 0.25f * B[band][1] + 0.75f * B[band][2];
            h[rr][band][3] = 0.75f * B[band][2] + 0.25f * B[band][3];
        }
    }

    // ---- Vertical interp + stores for bands 1..4 ----
    #pragma unroll
    for (int band = 0; band < 4; band++) {
        float4 o_top, o_bot;
        o_top.x = 0.25f * h[0][band][0] + 0.75f * h[1][band][0];
        o_top.y = 0.25f * h[0][band][1] + 0.75f * h[1][band][1];
        o_top.z = 0.25f * h[0][band][2] + 0.75f * h[1][band][2];
        o_top.w = 0.25f * h[0][band][3] + 0.75f * h[1][band][3];
        o_bot.x = 0.75f * h[1][band][0] + 0.25f * h[2][band][0];
        o_bot.y = 0.75f * h[1][band][1] + 0.25f * h[2][band][1];
        o_bot.z = 0.75f * h[1][band][2] + 0.25f * h[2][band][2];
        o_bot.w = 0.75f * h[1][band][3] + 0.25f * h[2][band][3];

        float* __restrict__ obp = op + (size_t)(band + 1) * 512 * 512;
        __stcs((float4*)(obp + row_t + colo), o_top);
        __stcs((float4*)(obp + row_b + colo), o_bot);
    }
}

extern "C" void kernel_launch(void* const* d_in, const int* in_sizes, int n_in,
                              void* d_out, int out_size) {
    const float* x = (const float*)d_in[0];
    float* out = (float*)d_out;
    dim3 block(BX, BY);
    dim3 grid(256 / TSX, 256 / TSY, 16 * 3);
    wavelet_kernel<<<grid, block>>>(x, out);
}

// round 6
// speedup vs baseline: 1.0167x; 1.0167x over previous
#include <cuda_runtime.h>
#include <cuda_bf16.h>

// WaveletTransform: x (16,3,512,512) f32 ->
//   per (b,c): [x, up(LL), up(LH), up(HL), up(HH)] -> out (16,15,512,512) f32
// Haar 2x2 analysis + 2x bilinear upsample (half-pixel centers, clamp edges).
// R4 structure (smem tile, early passthrough) with write-through output stores
// (__stwt) to bypass L2 dirty accumulation and smooth the DRAM write stream.

#define BX 16           // threads x (each covers 2 sub-cells)
#define BY 8            // threads y
#define TSX 32          // sub-cells per tile, x
#define TSY 8           // sub-cells per tile, y
#define HPX (TSX + 2)   // 34 halo cols
#define HPY (TSY + 2)   // 10 halo rows

__global__ __launch_bounds__(BX * BY)
void wavelet_kernel(const float* __restrict__ x, float* __restrict__ out) {
    const int plane = blockIdx.z;           // b*3 + c
    const int b = plane / 3;
    const int c = plane - 3 * b;
    const float* __restrict__ xp = x + (size_t)plane * 512 * 512;
    float* __restrict__ op = out + ((size_t)b * 15 + (size_t)c * 5) * 512 * 512;

    __shared__ float s[4][HPY][HPX];

    const int sx0 = blockIdx.x * TSX;
    const int sy0 = blockIdx.y * TSY;
    const int tid = threadIdx.y * BX + threadIdx.x;

    // This thread owns sub-cells (sy, sxp) and (sy, sxp+1).
    const int sxp = sx0 + 2 * threadIdx.x;      // first sub-cell x in [0,256)
    const int sy  = sy0 + threadIdx.y;
    const size_t row_t = (size_t)(2 * sy) * 512;
    const size_t row_b = (size_t)(2 * sy + 1) * 512;
    const size_t colo  = (size_t)(2 * sxp);     // first output col (16B aligned)

    // ---- Band 0: passthrough copy, issued first (no smem dependency) ----
    {
        const float4 t0 = *((const float4*)(xp + row_t + colo));
        const float4 t1 = *((const float4*)(xp + row_b + colo));
        __stwt((float4*)(op + row_t + colo), t0);
        __stwt((float4*)(op + row_b + colo), t1);
    }

    // ---- Phase 1: Haar bands for sub-tile + 1 halo, edge-clamped ----
    #pragma unroll
    for (int idx = tid; idx < HPY * HPX; idx += BX * BY) {
        const int hy = idx / HPX;
        const int hx = idx - hy * HPX;
        int gsy = sy0 - 1 + hy; gsy = min(max(gsy, 0), 255);
        int gsx = sx0 - 1 + hx; gsx = min(max(gsx, 0), 255);
        const float2 t0 = *((const float2*)(xp + (size_t)(2 * gsy)     * 512) + gsx);
        const float2 t1 = *((const float2*)(xp + (size_t)(2 * gsy + 1) * 512) + gsx);
        const float a = t0.x, bb = t0.y, cc = t1.x, dd = t1.y;
        s[0][hy][hx] = (a + bb + cc + dd) * 0.5f;   // LL
        s[1][hy][hx] = (a + bb - cc - dd) * 0.5f;   // LH
        s[2][hy][hx] = (a - bb + cc - dd) * 0.5f;   // HL
        s[3][hy][hx] = (a - bb - cc + dd) * 0.5f;   // HH
    }
    __syncthreads();

    const int lx = 1 + 2 * threadIdx.x;         // smem x of first sub-cell
    const int ly = 1 + threadIdx.y;

    // ---- Bands 1..4: separable bilinear 2x upsample ----
    // even out col: 0.25*prev + 0.75*cur ; odd: 0.75*cur + 0.25*next
    #pragma unroll
    for (int band = 0; band < 4; band++) {
        // rows ly-1, ly, ly+1 ; cols lx-1..lx+2 as two float2 each
        float h[3][4];
        #pragma unroll
        for (int r = 0; r < 3; r++) {
            const float* row = &s[band][ly - 1 + r][0];
            const float2 p0 = *((const float2*)(row + lx - 1));  // lx-1, lx
            const float2 p1 = *((const float2*)(row + lx + 1));  // lx+1, lx+2
            h[r][0] = 0.25f * p0.x + 0.75f * p0.y;
            h[r][1] = 0.75f * p0.y + 0.25f * p1.x;
            h[r][2] = 0.25f * p0.y + 0.75f * p1.x;
            h[r][3] = 0.75f * p1.x + 0.25f * p1.y;
        }
        float4 o_top, o_bot;
        o_top.x = 0.25f * h[0][0] + 0.75f * h[1][0];
        o_top.y = 0.25f * h[0][1] + 0.75f * h[1][1];
        o_top.z = 0.25f * h[0][2] + 0.75f * h[1][2];
        o_top.w = 0.25f * h[0][3] + 0.75f * h[1][3];
        o_bot.x = 0.75f * h[1][0] + 0.25f * h[2][0];
        o_bot.y = 0.75f * h[1][1] + 0.25f * h[2][1];
        o_bot.z = 0.75f * h[1][2] + 0.25f * h[2][2];
        o_bot.w = 0.75f * h[1][3] + 0.25f * h[2][3];

        float* __restrict__ obp = op + (size_t)(band + 1) * 512 * 512;
        __stwt((float4*)(obp + row_t + colo), o_top);
        __stwt((float4*)(obp + row_b + colo), o_bot);
    }
}

extern "C" void kernel_launch(void* const* d_in, const int* in_sizes, int n_in,
                              void* d_out, int out_size) {
    const float* x = (const float*)d_in[0];
    float* out = (float*)d_out;
    dim3 block(BX, BY);
    dim3 grid(256 / TSX, 256 / TSY, 16 * 3);
    wavelet_kernel<<<grid, block>>>(x, out);
}

// round 7
// speedup vs baseline: 1.0180x; 1.0013x over previous
#include <cuda_runtime.h>
#include <cuda_bf16.h>

// WaveletTransform: x (16,3,512,512) f32 ->
//   per (b,c): [x, up(LL), up(LH), up(HL), up(HH)] -> out (16,15,512,512) f32
// Haar 2x2 analysis + 2x bilinear upsample (half-pixel centers, clamp edges).
// Full-row tiles: each CTA (256 thr) covers the entire 512-px row width x
// 4 output rows, so every output row is written as one contiguous 2KB burst
// by 4 warps of the same CTA (DRAM row-buffer friendly writes).

#define BX 128          // threads x (each covers 2 sub-cells) -> full 256 sub-cols
#define BY 2            // threads y
#define TSY 2           // sub-rows per tile
#define HPX 258         // 256 sub-cols + 2 halo
#define HPY (TSY + 2)   // 4 halo rows
#define SPITCH 260      // smem row pitch (even -> 8B-aligned float2)

__global__ __launch_bounds__(BX * BY)
void wavelet_kernel(const float* __restrict__ x, float* __restrict__ out) {
    const int plane = blockIdx.z;           // b*3 + c
    const int b = plane / 3;
    const int c = plane - 3 * b;
    const float* __restrict__ xp = x + (size_t)plane * 512 * 512;
    float* __restrict__ op = out + ((size_t)b * 15 + (size_t)c * 5) * 512 * 512;

    __shared__ float s[4][HPY][SPITCH];

    const int sy0 = blockIdx.y * TSY;
    const int tid = threadIdx.y * BX + threadIdx.x;

    // This thread owns sub-cells (sy, sxp) and (sy, sxp+1).
    const int sxp = 2 * threadIdx.x;            // [0,256) even
    const int sy  = sy0 + threadIdx.y;
    const size_t row_t = (size_t)(2 * sy) * 512;
    const size_t row_b = (size_t)(2 * sy + 1) * 512;
    const size_t colo  = (size_t)(2 * sxp);     // first output col (16B aligned)

    // ---- Band 0: passthrough copy, issued first (no smem dependency) ----
    {
        const float4 t0 = *((const float4*)(xp + row_t + colo));
        const float4 t1 = *((const float4*)(xp + row_b + colo));
        __stcs((float4*)(op + row_t + colo), t0);
        __stcs((float4*)(op + row_b + colo), t1);
    }

    // ---- Phase 1: Haar bands for 4 halo sub-rows x 258 cols, edge-clamped ----
    for (int idx = tid; idx < HPY * HPX; idx += BX * BY) {
        const int hy = idx / HPX;
        const int hx = idx - hy * HPX;
        int gsy = sy0 - 1 + hy; gsy = min(max(gsy, 0), 255);
        int gsx = hx - 1;       gsx = min(max(gsx, 0), 255);
        const float2 t0 = *((const float2*)(xp + (size_t)(2 * gsy)     * 512) + gsx);
        const float2 t1 = *((const float2*)(xp + (size_t)(2 * gsy + 1) * 512) + gsx);
        const float a = t0.x, bb = t0.y, cc = t1.x, dd = t1.y;
        s[0][hy][hx] = (a + bb + cc + dd) * 0.5f;   // LL
        s[1][hy][hx] = (a + bb - cc - dd) * 0.5f;   // LH
        s[2][hy][hx] = (a - bb + cc - dd) * 0.5f;   // HL
        s[3][hy][hx] = (a - bb - cc + dd) * 0.5f;   // HH
    }
    __syncthreads();

    const int lx = 1 + 2 * threadIdx.x;         // smem x of first sub-cell
    const int ly = 1 + threadIdx.y;

    // ---- Bands 1..4: separable bilinear 2x upsample ----
    // even out col: 0.25*prev + 0.75*cur ; odd: 0.75*cur + 0.25*next
    #pragma unroll
    for (int band = 0; band < 4; band++) {
        float h[3][4];
        #pragma unroll
        for (int r = 0; r < 3; r++) {
            const float* row = &s[band][ly - 1 + r][0];
            const float2 p0 = *((const float2*)(row + lx - 1));  // lx-1, lx
            const float2 p1 = *((const float2*)(row + lx + 1));  // lx+1, lx+2
            h[r][0] = 0.25f * p0.x + 0.75f * p0.y;
            h[r][1] = 0.75f * p0.y + 0.25f * p1.x;
            h[r][2] = 0.25f * p0.y + 0.75f * p1.x;
            h[r][3] = 0.75f * p1.x + 0.25f * p1.y;
        }
        float4 o_top, o_bot;
        o_top.x = 0.25f * h[0][0] + 0.75f * h[1][0];
        o_top.y = 0.25f * h[0][1] + 0.75f * h[1][1];
        o_top.z = 0.25f * h[0][2] + 0.75f * h[1][2];
        o_top.w = 0.25f * h[0][3] + 0.75f * h[1][3];
        o_bot.x = 0.75f * h[1][0] + 0.25f * h[2][0];
        o_bot.y = 0.75f * h[1][1] + 0.25f * h[2][1];
        o_bot.z = 0.75f * h[1][2] + 0.25f * h[2][2];
        o_bot.w = 0.75f * h[1][3] + 0.25f * h[2][3];

        float* __restrict__ obp = op + (size_t)(band + 1) * 512 * 512;
        __stcs((float4*)(obp + row_t + colo), o_top);
        __stcs((float4*)(obp + row_b + colo), o_bot);
    }
}

extern "C" void kernel_launch(void* const* d_in, const int* in_sizes, int n_in,
                              void* d_out, int out_size) {
    const float* x = (const float*)d_in[0];
    float* out = (float*)d_out;
    dim3 block(BX, BY);
    dim3 grid(1, 256 / TSY, 16 * 3);
    wavelet_kernel<<<grid, block>>>(x, out);
}